// round 4
// baseline (speedup 1.0000x reference)
#include <cuda_runtime.h>
#include <cuda_bf16.h>
#include <cstdint>

// Problem constants (fixed-shape problem; buffers sized to these)
#define MAXN 100000
#define MAXE 1600000
#define F    128
#define CAP  96          // padded-CSR capacity per node (Poisson(16) max ~45)

// ---------------- scratch (device globals: no allocation allowed) -------------
__device__ float g_agg[MAXN * F];       // aggregation output / MLP input
__device__ float g_h1 [MAXN * F];       // hidden after MLP1
__device__ int   g_deg[MAXN];
__device__ int   g_col[MAXN * CAP];
__device__ int   g_cnt[128];            // per-graph node counts

// ---------------- zero scratch + pool region ----------------------------------
__global__ void zero_kernel(float* pool, int N, int PG) {
    int i = blockIdx.x * blockDim.x + threadIdx.x;
    if (i < N)   g_deg[i] = 0;
    if (i < PG)  pool[i] = 0.f;
    if (i < 128) g_cnt[i] = 0;
}

// ---------------- build padded CSR (dst -> list of src) -----------------------
__global__ void fill_kernel(const int* __restrict__ ei, int E, int N) {
    int e = blockIdx.x * blockDim.x + threadIdx.x;
    if (e >= E) return;
    int s = ei[e];          // src
    int d = ei[E + e];      // dst
    int slot = atomicAdd(&g_deg[d], 1);
    if (slot < CAP) g_col[d * CAP + slot] = s;
}

// ---------------- GIN aggregation: out[i] = in[i] + sum_{j in N(i)} in[j] -----
__global__ void agg_kernel(const float* __restrict__ in, float* __restrict__ out, int N) {
    int warp = (blockIdx.x * blockDim.x + threadIdx.x) >> 5;
    int lane = threadIdx.x & 31;
    if (warp >= N) return;
    const float4* xv = (const float4*)in;
    float4 acc = xv[(size_t)warp * 32 + lane];
    int d = g_deg[warp];
    if (d > CAP) d = CAP;
    const int* cl = g_col + (size_t)warp * CAP;
#pragma unroll 2
    for (int e = 0; e < d; e++) {
        int c = cl[e];
        float4 v = xv[(size_t)c * 32 + lane];
        acc.x += v.x; acc.y += v.y; acc.z += v.z; acc.w += v.w;
    }
    ((float4*)out)[(size_t)warp * 32 + lane] = acc;
}

// ---------------- fused 2-layer MLP: out = relu(relu(in@Wa^T+ba)@Wb^T+bb) -----
// Block: 256 threads, 128 rows. smem: input tile [128][132] + W^T tile [128][132].
#define STR 132
#define MLP_SMEM (2 * 128 * STR * 4)

__global__ __launch_bounds__(256) void mlp_kernel(
    const float* __restrict__ in,
    const float* __restrict__ Wa, const float* __restrict__ ba,
    const float* __restrict__ Wb, const float* __restrict__ bb,
    float* __restrict__ out, int N)
{
    extern __shared__ float smem[];
    float* s_in = smem;               // [128][STR], features k contiguous
    float* s_w  = smem + 128 * STR;   // [128][STR], transposed: s_w[k][o] = W[o][k]

    int tid = threadIdx.x;
    int tx = tid & 15, ty = tid >> 4;        // 16x16 thread grid
    int row0 = blockIdx.x * 128;

    // load input tile (clamped rows for tail block; stores are guarded later)
    for (int v = tid; v < 128 * 32; v += 256) {
        int r = v >> 5, k4 = v & 31;
        int gr = row0 + r; if (gr >= N) gr = N - 1;
        float4 val = *(const float4*)(in + (size_t)gr * F + k4 * 4);
        *(float4*)(s_in + r * STR + k4 * 4) = val;
    }
    // load Wa transposed (contiguous smem writes)
    for (int v = tid; v < 128 * 128; v += 256) {
        int k = v >> 7, o = v & 127;
        s_w[k * STR + o] = __ldg(Wa + o * F + k);
    }
    float bja[8], bjb[8];
#pragma unroll
    for (int j = 0; j < 8; j++) {
        bja[j] = __ldg(ba + tx * 8 + j);
        bjb[j] = __ldg(bb + tx * 8 + j);
    }
    __syncthreads();

    float acc[8][8];

    // ------- layer 1 -------
#pragma unroll
    for (int i = 0; i < 8; i++)
#pragma unroll
        for (int j = 0; j < 8; j++) acc[i][j] = 0.f;

#pragma unroll 2
    for (int k = 0; k < 128; k += 4) {
        float4 a4[8];
#pragma unroll
        for (int i = 0; i < 8; i++)
            a4[i] = *(float4*)(s_in + (ty * 8 + i) * STR + k);
#pragma unroll
        for (int kk = 0; kk < 4; kk++) {
            float4 b0 = *(float4*)(s_w + (k + kk) * STR + tx * 8);
            float4 b1 = *(float4*)(s_w + (k + kk) * STR + tx * 8 + 4);
            float bv0 = b0.x, bv1 = b0.y, bv2 = b0.z, bv3 = b0.w;
            float bv4 = b1.x, bv5 = b1.y, bv6 = b1.z, bv7 = b1.w;
#pragma unroll
            for (int i = 0; i < 8; i++) {
                float av = ((const float*)&a4[i])[kk];
                acc[i][0] = fmaf(av, bv0, acc[i][0]);
                acc[i][1] = fmaf(av, bv1, acc[i][1]);
                acc[i][2] = fmaf(av, bv2, acc[i][2]);
                acc[i][3] = fmaf(av, bv3, acc[i][3]);
                acc[i][4] = fmaf(av, bv4, acc[i][4]);
                acc[i][5] = fmaf(av, bv5, acc[i][5]);
                acc[i][6] = fmaf(av, bv6, acc[i][6]);
                acc[i][7] = fmaf(av, bv7, acc[i][7]);
            }
        }
    }
    __syncthreads();   // everyone done reading s_in / s_w

    // mid = relu(acc + ba) -> back into s_in; refill s_w with Wb
#pragma unroll
    for (int i = 0; i < 8; i++) {
        float4 v0, v1;
        v0.x = fmaxf(acc[i][0] + bja[0], 0.f);
        v0.y = fmaxf(acc[i][1] + bja[1], 0.f);
        v0.z = fmaxf(acc[i][2] + bja[2], 0.f);
        v0.w = fmaxf(acc[i][3] + bja[3], 0.f);
        v1.x = fmaxf(acc[i][4] + bja[4], 0.f);
        v1.y = fmaxf(acc[i][5] + bja[5], 0.f);
        v1.z = fmaxf(acc[i][6] + bja[6], 0.f);
        v1.w = fmaxf(acc[i][7] + bja[7], 0.f);
        *(float4*)(s_in + (ty * 8 + i) * STR + tx * 8)     = v0;
        *(float4*)(s_in + (ty * 8 + i) * STR + tx * 8 + 4) = v1;
    }
    for (int v = tid; v < 128 * 128; v += 256) {
        int k = v >> 7, o = v & 127;
        s_w[k * STR + o] = __ldg(Wb + o * F + k);
    }
    __syncthreads();

    // ------- layer 2 -------
#pragma unroll
    for (int i = 0; i < 8; i++)
#pragma unroll
        for (int j = 0; j < 8; j++) acc[i][j] = 0.f;

#pragma unroll 2
    for (int k = 0; k < 128; k += 4) {
        float4 a4[8];
#pragma unroll
        for (int i = 0; i < 8; i++)
            a4[i] = *(float4*)(s_in + (ty * 8 + i) * STR + k);
#pragma unroll
        for (int kk = 0; kk < 4; kk++) {
            float4 b0 = *(float4*)(s_w + (k + kk) * STR + tx * 8);
            float4 b1 = *(float4*)(s_w + (k + kk) * STR + tx * 8 + 4);
            float bv0 = b0.x, bv1 = b0.y, bv2 = b0.z, bv3 = b0.w;
            float bv4 = b1.x, bv5 = b1.y, bv6 = b1.z, bv7 = b1.w;
#pragma unroll
            for (int i = 0; i < 8; i++) {
                float av = ((const float*)&a4[i])[kk];
                acc[i][0] = fmaf(av, bv0, acc[i][0]);
                acc[i][1] = fmaf(av, bv1, acc[i][1]);
                acc[i][2] = fmaf(av, bv2, acc[i][2]);
                acc[i][3] = fmaf(av, bv3, acc[i][3]);
                acc[i][4] = fmaf(av, bv4, acc[i][4]);
                acc[i][5] = fmaf(av, bv5, acc[i][5]);
                acc[i][6] = fmaf(av, bv6, acc[i][6]);
                acc[i][7] = fmaf(av, bv7, acc[i][7]);
            }
        }
    }

    // epilogue: out = relu(acc + bb)
#pragma unroll
    for (int i = 0; i < 8; i++) {
        int gr = row0 + ty * 8 + i;
        if (gr < N) {
            float4 v0, v1;
            v0.x = fmaxf(acc[i][0] + bjb[0], 0.f);
            v0.y = fmaxf(acc[i][1] + bjb[1], 0.f);
            v0.z = fmaxf(acc[i][2] + bjb[2], 0.f);
            v0.w = fmaxf(acc[i][3] + bjb[3], 0.f);
            v1.x = fmaxf(acc[i][4] + bjb[4], 0.f);
            v1.y = fmaxf(acc[i][5] + bjb[5], 0.f);
            v1.z = fmaxf(acc[i][6] + bjb[6], 0.f);
            v1.w = fmaxf(acc[i][7] + bjb[7], 0.f);
            *(float4*)(out + (size_t)gr * F + tx * 8)     = v0;
            *(float4*)(out + (size_t)gr * F + tx * 8 + 4) = v1;
        }
    }
}

// ---------------- pooling: counts (run-length over sorted batch) --------------
__global__ void pool_count(const int* __restrict__ batch, int N) {
    int chunk = blockIdx.x * blockDim.x + threadIdx.x;
    int n0 = chunk * 16;
    if (n0 >= N) return;
    int nend = min(n0 + 16, N);
    int curg = batch[n0];
    int c = 0;
    for (int n = n0; n < nend; n++) {
        int g = batch[n];
        if (g != curg) { atomicAdd(&g_cnt[curg], c); c = 0; curg = g; }
        c++;
    }
    atomicAdd(&g_cnt[curg], c);
}

// ---------------- pooling: sums (16 nodes per thread, run-length merge) -------
__global__ void pool_sum(const float* __restrict__ h, const int* __restrict__ batch,
                         float* __restrict__ pool, int N) {
    int t = blockIdx.x * blockDim.x + threadIdx.x;
    int f = t & 127;
    int chunk = t >> 7;
    int n0 = chunk * 16;
    if (n0 >= N) return;
    int nend = min(n0 + 16, N);
    int curg = batch[n0];
    float acc = 0.f;
    for (int n = n0; n < nend; n++) {
        int g = batch[n];
        if (g != curg) { atomicAdd(&pool[curg * F + f], acc); acc = 0.f; curg = g; }
        acc += h[(size_t)n * F + f];
    }
    atomicAdd(&pool[curg * F + f], acc);
}

__global__ void fin_kernel(float* __restrict__ pool, int PG) {
    int i = blockIdx.x * blockDim.x + threadIdx.x;
    if (i < PG) {
        float c = (float)g_cnt[i >> 7];
        pool[i] = pool[i] / fmaxf(c, 1.f);
    }
}

// ---------------- launch ------------------------------------------------------
extern "C" void kernel_launch(void* const* d_in, const int* in_sizes, int n_in,
                              void* d_out, int out_size) {
    const float* x  = (const float*)d_in[0];
    const int*   ei = (const int*)  d_in[1];   // [2, E], int32
    const int*   bt = (const int*)  d_in[2];   // [N], int32, sorted
    const float* W1 = (const float*)d_in[3];
    const float* b1 = (const float*)d_in[4];
    const float* W2 = (const float*)d_in[5];
    const float* b2 = (const float*)d_in[6];
    const float* W3 = (const float*)d_in[7];
    const float* b3 = (const float*)d_in[8];
    const float* W4 = (const float*)d_in[9];
    const float* b4 = (const float*)d_in[10];
    float* outp = (float*)d_out;

    int N = in_sizes[0] / F;          // 100000
    int E = in_sizes[1] / 2;          // 1600000
    int PG = out_size - N * F;        // 100*128 = 12800 (pool region size)
    float* h_out = outp + PG;         // final h goes straight into output

    cudaFuncSetAttribute(mlp_kernel, cudaFuncAttributeMaxDynamicSharedMemorySize, MLP_SMEM);

    // scratch pointers (device globals)
    float* agg; cudaGetSymbolAddress((void**)&agg, g_agg);
    float* h1;  cudaGetSymbolAddress((void**)&h1,  g_h1);

    int zt = (N > PG ? N : PG);
    zero_kernel<<<(zt + 255) / 256, 256>>>(outp, N, PG);
    fill_kernel<<<(E + 255) / 256, 256>>>(ei, E, N);

    int aggBlocks = (N * 32 + 255) / 256;
    int mlpBlocks = (N + 127) / 128;

    // conv1
    agg_kernel<<<aggBlocks, 256>>>(x, agg, N);
    mlp_kernel<<<mlpBlocks, 256, MLP_SMEM>>>(agg, W1, b1, W2, b2, h1, N);
    // conv2
    agg_kernel<<<aggBlocks, 256>>>(h1, agg, N);
    mlp_kernel<<<mlpBlocks, 256, MLP_SMEM>>>(agg, W3, b3, W4, b4, h_out, N);

    // global mean pool
    int chunks = (N + 15) / 16;
    pool_count<<<(chunks + 255) / 256, 256>>>(bt, N);
    pool_sum<<<(chunks * F + 255) / 256, 256>>>(h_out, bt, outp, N);
    fin_kernel<<<(PG + 255) / 256, 256>>>(outp, PG);
}